// round 9
// baseline (speedup 1.0000x reference)
#include <cuda_runtime.h>
#include <cuda_bf16.h>

#define BATCH 16384
#define FEAT 512
#define NCLS 100000
#define ALPHA 0.5f
#define LAMDA 0.003f

// Block layout of the mega kernel: copy blocks first (pure bandwidth, ramps
// DRAM immediately), fused blocks after.
#define FUSED_BLOCKS (BATCH / 2)                       // 8192 (2 samples/block)
#define COPY_CHUNKS  (NCLS * (FEAT / 4) / 4)           // 3,200,000 64B chunks
#define COPY_BLOCKS  ((COPY_CHUNKS + 255) / 256)       // 12500

// Scratch: per-class sample counts (allocation-free __device__ global).
__device__ int g_counts[NCLS];

__global__ void zero_counts_kernel() {
    int i = blockIdx.x * blockDim.x + threadIdx.x;
    if (i < NCLS) g_counts[i] = 0;
}

__global__ void count_kernel(const int* __restrict__ targets) {
    int i = blockIdx.x * blockDim.x + threadIdx.x;
    if (i < BATCH) atomicAdd(&g_counts[targets[i]], 1);
}

// One grid doing both jobs so the DRAM pipe never drains:
//  - blocks [0, COPY_BLOCKS): streaming copy of center rows, skipping
//    cnt==1 rows (owned by the fused half). cnt>1 rows ARE copied (they
//    are the accumulation base for dup_kernel, which runs after).
//  - blocks [COPY_BLOCKS, +FUSED_BLOCKS): loss/tw + direct center rewrite
//    for cnt==1 classes.
__global__ __launch_bounds__(256) void mega_kernel(
    const float4* __restrict__ inputs,
    const float4* __restrict__ centers,
    const float*  __restrict__ wpc,
    const int*    __restrict__ targets,
    float4* __restrict__ loss_out,
    float4* __restrict__ tw_out,
    float4* __restrict__ new_centers) {

    const int bid = blockIdx.x;

    if (bid < COPY_BLOCKS) {
        // ---- copy half: 64B (4 float4) per thread, one row per thread ----
        const int tchunk = bid * 256 + threadIdx.x;
        const size_t i = (size_t)tchunk * 4;        // float4 index
        const int row = (int)(i >> 7);              // 128 float4 per row
        if (row >= NCLS) return;
        if (g_counts[row] == 1) return;             // fused half owns it
        float4 v0 = __ldcs(&centers[i + 0]);
        float4 v1 = __ldcs(&centers[i + 1]);
        float4 v2 = __ldcs(&centers[i + 2]);
        float4 v3 = __ldcs(&centers[i + 3]);
        __stcs(&new_centers[i + 0], v0);
        __stcs(&new_centers[i + 1], v1);
        __stcs(&new_centers[i + 2], v2);
        __stcs(&new_centers[i + 3], v3);
    } else {
        // ---- fused half: 2 samples per block, 128 threads each ----
        const int fbid  = bid - COPY_BLOCKS;
        const int group = threadIdx.x >> 7;         // 0..1
        const int d4    = threadIdx.x & 127;        // 0..127
        const int b = fbid * 2 + group;

        const int t   = __ldg(&targets[b]);
        const int cnt = g_counts[t];
        const float w = LAMDA * __ldg(&wpc[t]);
        const float s = ALPHA / (1.0f + (float)cnt);

        const size_t ib = (size_t)b * (FEAT / 4) + d4;
        const size_t ic = (size_t)t * (FEAT / 4) + d4;
        const float4 x = inputs[ib];
        const float4 c = centers[ic];

        float4 l;
        float dx;
        dx = x.x - c.x; l.x = 0.5f * dx * dx;
        dx = x.y - c.y; l.y = 0.5f * dx * dx;
        dx = x.z - c.z; l.z = 0.5f * dx * dx;
        dx = x.w - c.w; l.w = 0.5f * dx * dx;

        loss_out[ib] = l;
        tw_out[ib]   = make_float4(w, w, w, w);

        if (cnt == 1) {
            // Sole sample of its class: full row rewrite, no atomics.
            new_centers[ic] = make_float4(c.x - s * x.x, c.y - s * x.y,
                                          c.z - s * x.z, c.w - s * x.w);
        }
        // cnt > 1: handled by dup_kernel after the base row is copied.
    }
}

// Post-pass for duplicate classes (~1.4k samples): accumulate -s*x onto the
// copied base row. Early-exit for the ~98.4% of samples with cnt==1.
__global__ __launch_bounds__(128) void dup_kernel(
    const float4* __restrict__ inputs,
    const int*    __restrict__ targets,
    float* __restrict__ new_centers) {

    const int b = blockIdx.x;
    const int t = __ldg(&targets[b]);
    const int cnt = g_counts[t];
    if (cnt <= 1) return;

    const float s = ALPHA / (1.0f + (float)cnt);
    const int d4 = threadIdx.x;
    const float4 x = inputs[(size_t)b * (FEAT / 4) + d4];
    float* dst = new_centers + (size_t)t * FEAT + d4 * 4;
    atomicAdd(dst + 0, -s * x.x);
    atomicAdd(dst + 1, -s * x.y);
    atomicAdd(dst + 2, -s * x.z);
    atomicAdd(dst + 3, -s * x.w);
}

extern "C" void kernel_launch(void* const* d_in, const int* in_sizes, int n_in,
                              void* d_out, int out_size) {
    const float* inputs  = (const float*)d_in[0];   // [BATCH, FEAT]
    const float* centers = (const float*)d_in[1];   // [NCLS, FEAT]
    const float* wpc     = (const float*)d_in[2];   // [NCLS]
    const int*   targets = (const int*)d_in[3];     // [BATCH]

    float* out  = (float*)d_out;
    float* loss = out;                                  // [BATCH, FEAT]
    float* tw   = out + (size_t)BATCH * FEAT;           // [BATCH, FEAT]
    float* newc = out + (size_t)2 * BATCH * FEAT;       // [NCLS, FEAT]

    zero_counts_kernel<<<(NCLS + 255) / 256, 256>>>();
    count_kernel<<<(BATCH + 255) / 256, 256>>>(targets);

    mega_kernel<<<COPY_BLOCKS + FUSED_BLOCKS, 256>>>(
        (const float4*)inputs, (const float4*)centers, wpc, targets,
        (float4*)loss, (float4*)tw, (float4*)newc);

    dup_kernel<<<BATCH, 128>>>((const float4*)inputs, targets, newc);
}